// round 15
// baseline (speedup 1.0000x reference)
#include <cuda_runtime.h>
#include <cuda_bf16.h>
#include <math.h>
#include <stdint.h>

#define NN 20000
#define EE 320000
#define TOTE (EE + NN)
#define HEADS 8
#define HID 32
#define OUTC 128
#define D0 256
#define D2 1024
#define NPART 79                 // ceil(NN/256)

// ---------------- scratch ---------------------------------------------------
__device__ float g_h[(size_t)NN * D2];
__device__ float g_feat[(size_t)NN * D0];
__device__ float g_res[(size_t)NN * D0];
__device__ float g_als[NN * HEADS];
__device__ float g_ald[NN * HEADS];
__device__ float g_alsP[(size_t)4 * NN * HEADS];
__device__ float g_aldP[(size_t)4 * NN * HEADS];
__device__ float g_alpha[(size_t)TOTE * HEADS];
__device__ int   g_deg[NN];
__device__ int   g_rowptr[NN + 1];
__device__ int   g_cursor[NN];
__device__ int   g_col[TOTE];
__device__ int   g_is32;
__device__ int   g_part[NPART];

// bf16 split operands
__device__ __nv_bfloat16 g_ahi[(size_t)NN * D0];
__device__ __nv_bfloat16 g_alo[(size_t)NN * D0];
#define WSZ 393216
#define OFF_W0  0u            // 512 rows x 64  (W0 cols 0-255, rW0 cols 256-511)
#define OFF_RW0 16384u
#define OFF_W1  32768u        // 256 rows x 256
#define OFF_W2  98304u        // 1152 rows x 256 (W2 cols 0-1023, rW2 cols 1024-1151)
#define OFF_RW2 360448u
__device__ __nv_bfloat16 g_whi[WSZ];
__device__ __nv_bfloat16 g_wlo[WSZ];

// ---------------- helpers ----------------------------------------------------
__device__ __forceinline__ uint32_t smem_u32(const void* p) {
    uint32_t r;
    asm("{ .reg .u64 t; cvta.to.shared.u64 t, %1; cvt.u32.u64 %0, t; }" : "=r"(r) : "l"(p));
    return r;
}

__device__ __forceinline__ void ldsm4(uint32_t* r, uint32_t addr) {
    asm volatile("ldmatrix.sync.aligned.m8n8.x4.shared.b16 {%0,%1,%2,%3}, [%4];"
                 : "=r"(r[0]), "=r"(r[1]), "=r"(r[2]), "=r"(r[3]) : "r"(addr));
}
__device__ __forceinline__ void ldsm2(uint32_t* r, uint32_t addr) {
    asm volatile("ldmatrix.sync.aligned.m8n8.x2.shared.b16 {%0,%1}, [%2];"
                 : "=r"(r[0]), "=r"(r[1]) : "r"(addr));
}
__device__ __forceinline__ void mma16816(float* c, const uint32_t* a, const uint32_t* b) {
    asm volatile("mma.sync.aligned.m16n8k16.row.col.f32.bf16.bf16.f32 "
                 "{%0,%1,%2,%3}, {%4,%5,%6,%7}, {%8,%9}, {%0,%1,%2,%3};"
                 : "+f"(c[0]), "+f"(c[1]), "+f"(c[2]), "+f"(c[3])
                 : "r"(a[0]), "r"(a[1]), "r"(a[2]), "r"(a[3]), "r"(b[0]), "r"(b[1]));
}

// ---------------- edge dtype detection -------------------------------------
__global__ void k_detect(const unsigned long long* __restrict__ p) {
    int i = blockIdx.x * blockDim.x + threadIdx.x;
    bool big = false;
    for (int j = i; j < EE; j += gridDim.x * blockDim.x)
        if (p[j] >= (unsigned long long)NN) big = true;
    if (__syncthreads_or(big) && threadIdx.x == 0) atomicOr(&g_is32, 1);
}

__device__ __forceinline__ int edge_at(const void* ei, int idx) {
    if (g_is32) return ((const int*)ei)[idx];
    return (int)((const long long*)ei)[idx];
}

// ---------------- CSR build -------------------------------------------------
__global__ void k_deg_init() {
    int i = blockIdx.x * blockDim.x + threadIdx.x;
    if (i < NN) g_deg[i] = 1;
    if (i == 0) g_is32 = 0;
}

__global__ void k_count(const void* __restrict__ ei) {
    int e = blockIdx.x * blockDim.x + threadIdx.x;
    if (e < EE) atomicAdd(&g_deg[edge_at(ei, EE + e)], 1);
}

__global__ void k_scanA() {
    __shared__ int sh[256];
    int i = blockIdx.x * 256 + threadIdx.x;
    sh[threadIdx.x] = (i < NN) ? g_deg[i] : 0;
    __syncthreads();
    for (int o = 128; o; o >>= 1) {
        if (threadIdx.x < o) sh[threadIdx.x] += sh[threadIdx.x + o];
        __syncthreads();
    }
    if (threadIdx.x == 0) g_part[blockIdx.x] = sh[0];
}

__global__ void k_scanB() {
    __shared__ int s[NPART];
    int t = threadIdx.x;
    if (t < NPART) s[t] = g_part[t];
    __syncthreads();
    if (t == 0) {
        int run = 0;
        for (int i = 0; i < NPART; i++) { int v = s[i]; s[i] = run; run += v; }
        g_rowptr[NN] = run;
    }
    __syncthreads();
    if (t < NPART) g_part[t] = s[t];
}

__global__ void k_scanC() {
    __shared__ int sh[256];
    int i = blockIdx.x * 256 + threadIdx.x;
    int v = (i < NN) ? g_deg[i] : 0;
    sh[threadIdx.x] = v;
    __syncthreads();
    for (int o = 1; o < 256; o <<= 1) {
        int a = (threadIdx.x >= o) ? sh[threadIdx.x - o] : 0;
        __syncthreads();
        sh[threadIdx.x] += a;
        __syncthreads();
    }
    if (i < NN) {
        int ex = sh[threadIdx.x] - v + g_part[blockIdx.x];
        g_rowptr[i] = ex;
        g_cursor[i] = ex;
    }
}

__global__ void k_fill(const void* __restrict__ ei) {
    int idx = blockIdx.x * blockDim.x + threadIdx.x;
    if (idx >= TOTE) return;
    int s, d;
    if (idx < EE) { s = edge_at(ei, idx); d = edge_at(ei, EE + idx); }
    else          { s = d = idx - EE; }
    int pos = atomicAdd(&g_cursor[d], 1);
    g_col[pos] = s;
}

// ---------------- bf16 split conversions ------------------------------------
__global__ void k_cvtA(const float* __restrict__ src, int Kt) {
    size_t idx = (size_t)blockIdx.x * blockDim.x + threadIdx.x;
    size_t tot = (size_t)NN * Kt;
    if (idx >= tot) return;
    float v = src[idx];
    __nv_bfloat16 hi = __float2bfloat16(v);
    g_ahi[idx] = hi;
    g_alo[idx] = __float2bfloat16(v - __bfloat162float(hi));
}

__global__ void k_cvtW(const float* __restrict__ W, unsigned woff, int K, int N) {
    int idx = blockIdx.x * blockDim.x + threadIdx.x;
    if (idx >= K * N) return;
    int k = idx / N, n = idx % N;
    float v = W[idx];
    __nv_bfloat16 hi = __float2bfloat16(v);
    g_whi[woff + (size_t)n * K + k] = hi;
    g_wlo[woff + (size_t)n * K + k] = __float2bfloat16(v - __bfloat162float(hi));
}

// ---------------- tensor-core GEMM via mma.sync (bf16 3-term split) ---------
// C cols [0,split) -> g_h (stride strideH); cols [split,..) -> g_res + bias.
// fuse=1: 32-wide heads, coef written directly to g_als/g_ald.
// fuse=2: 128-wide heads, per-quarter partials to g_alsP/g_aldP.
#define RP 40

__global__ __launch_bounds__(256) void k_mma(int Kt, unsigned woff,
                                             const float* __restrict__ bias,
                                             int split, int strideH, int strideR,
                                             int fuse,
                                             const float* __restrict__ a_s,
                                             const float* __restrict__ a_d) {
    __shared__ __nv_bfloat16 sAh[128 * RP], sAl[128 * RP];
    __shared__ __nv_bfloat16 sBh[64 * RP],  sBl[64 * RP];
    __shared__ float sAS[256], sAD[256];

    const int tid = threadIdx.x, lane = tid & 31, wid = tid >> 5;
    const int m0 = (wid & 3) << 5;
    const int n0 = (wid >> 2) << 5;
    const int bm = blockIdx.y * 128, bn = blockIdx.x * 64;

    const uint32_t aAh = smem_u32(sAh), aAl = smem_u32(sAl);
    const uint32_t aBh = smem_u32(sBh), aBl = smem_u32(sBl);

    if (fuse == 1) { sAS[tid] = a_s[tid]; sAD[tid] = a_d[tid]; }
    else if (fuse == 2 && bn < split && tid < 64) {
        sAS[tid] = a_s[bn + tid];
        sAD[tid] = a_d[bn + tid];
    }

    const int ar0 = tid >> 2, ac = (tid & 3) * 8;
    const int ar1 = (tid + 256) >> 2;
    const int br = tid >> 2;
    const int am0 = bm + ar0, am1 = bm + ar1;
    const size_t bb = (size_t)(bn + br) * Kt + ac;

    float acc[2][4][4] = {};
    uint4 pAh0, pAl0, pAh1, pAl1, pBh, pBl;
    const uint4 z4 = make_uint4(0, 0, 0, 0);

    pAh0 = (am0 < NN) ? *(const uint4*)(g_ahi + (size_t)am0 * Kt + ac) : z4;
    pAl0 = (am0 < NN) ? *(const uint4*)(g_alo + (size_t)am0 * Kt + ac) : z4;
    pAh1 = (am1 < NN) ? *(const uint4*)(g_ahi + (size_t)am1 * Kt + ac) : z4;
    pAl1 = (am1 < NN) ? *(const uint4*)(g_alo + (size_t)am1 * Kt + ac) : z4;
    pBh = *(const uint4*)(g_whi + woff + bb);
    pBl = *(const uint4*)(g_wlo + woff + bb);

    const int nch = Kt >> 5;
    for (int ch = 0; ch < nch; ch++) {
        *(uint4*)(sAh + ar0 * RP + ac) = pAh0;
        *(uint4*)(sAl + ar0 * RP + ac) = pAl0;
        *(uint4*)(sAh + ar1 * RP + ac) = pAh1;
        *(uint4*)(sAl + ar1 * RP + ac) = pAl1;
        *(uint4*)(sBh + br * RP + ac) = pBh;
        *(uint4*)(sBl + br * RP + ac) = pBl;
        __syncthreads();

        if (ch + 1 < nch) {
            const int k1 = (ch + 1) << 5;
            pAh0 = (am0 < NN) ? *(const uint4*)(g_ahi + (size_t)am0 * Kt + k1 + ac) : z4;
            pAl0 = (am0 < NN) ? *(const uint4*)(g_alo + (size_t)am0 * Kt + k1 + ac) : z4;
            pAh1 = (am1 < NN) ? *(const uint4*)(g_ahi + (size_t)am1 * Kt + k1 + ac) : z4;
            pAl1 = (am1 < NN) ? *(const uint4*)(g_alo + (size_t)am1 * Kt + k1 + ac) : z4;
            pBh = *(const uint4*)(g_whi + woff + bb + k1);
            pBl = *(const uint4*)(g_wlo + woff + bb + k1);
        }

#pragma unroll
        for (int ks = 0; ks < 32; ks += 16) {
            uint32_t ah[2][4], al[2][4], bh[4][2], bl[4][2];
#pragma unroll
            for (int mi = 0; mi < 2; mi++) {
                uint32_t off = (uint32_t)((m0 + mi * 16 + (lane & 15)) * RP
                                          + ks + ((lane >> 4) << 3)) * 2;
                ldsm4(ah[mi], aAh + off);
                ldsm4(al[mi], aAl + off);
            }
#pragma unroll
            for (int nj = 0; nj < 4; nj++) {
                uint32_t off = (uint32_t)((n0 + nj * 8 + (lane & 7)) * RP
                                          + ks + (((lane >> 3) & 1) << 3)) * 2;
                ldsm2(bh[nj], aBh + off);
                ldsm2(bl[nj], aBl + off);
            }
#pragma unroll
            for (int mi = 0; mi < 2; mi++)
#pragma unroll
                for (int nj = 0; nj < 4; nj++) {
                    mma16816(acc[mi][nj], ah[mi], bh[nj]);
                    mma16816(acc[mi][nj], ah[mi], bl[nj]);
                    mma16816(acc[mi][nj], al[mi], bh[nj]);
                }
        }
        __syncthreads();
    }

    // ---- epilogue ----
    const int wcol = bn + n0;
    const int side = wcol < split;
    const int hd = wcol >> 5;
    const int rbase = bm + m0 + (lane >> 2);
    float sPs[4] = {}, sPd[4] = {};

#pragma unroll
    for (int mi = 0; mi < 2; mi++) {
#pragma unroll
        for (int nj = 0; nj < 4; nj++) {
            int cg = wcol + nj * 8 + (lane & 3) * 2;
            int r0 = rbase + mi * 16, r1 = r0 + 8;
            float v0 = acc[mi][nj][0], v1 = acc[mi][nj][1];
            float v2 = acc[mi][nj][2], v3 = acc[mi][nj][3];
            if (side) {
                if (r0 < NN) *(float2*)(g_h + (size_t)r0 * strideH + cg) = make_float2(v0, v1);
                if (r1 < NN) *(float2*)(g_h + (size_t)r1 * strideH + cg) = make_float2(v2, v3);
                if (fuse) {
                    int cc = (fuse == 1) ? ((hd << 5) | (cg & 31)) : (cg - bn);
                    float as0 = sAS[cc], as1 = sAS[cc + 1];
                    float ad0 = sAD[cc], ad1 = sAD[cc + 1];
                    sPs[mi * 2 + 0] += v0 * as0 + v1 * as1;
                    sPs[mi * 2 + 1] += v2 * as0 + v3 * as1;
                    sPd[mi * 2 + 0] += v0 * ad0 + v1 * ad1;
                    sPd[mi * 2 + 1] += v2 * ad0 + v3 * ad1;
                }
            } else {
                int cr = cg - split;
                float bx = bias ? bias[cr] : 0.f;
                float by = bias ? bias[cr + 1] : 0.f;
                if (r0 < NN) *(float2*)(g_res + (size_t)r0 * strideR + cr) = make_float2(v0 + bx, v1 + by);
                if (r1 < NN) *(float2*)(g_res + (size_t)r1 * strideR + cr) = make_float2(v2 + bx, v3 + by);
            }
        }
    }

    if (side && fuse) {
#pragma unroll
        for (int q = 0; q < 4; q++) {
            sPs[q] += __shfl_xor_sync(0xffffffffu, sPs[q], 1);
            sPs[q] += __shfl_xor_sync(0xffffffffu, sPs[q], 2);
            sPd[q] += __shfl_xor_sync(0xffffffffu, sPd[q], 1);
            sPd[q] += __shfl_xor_sync(0xffffffffu, sPd[q], 2);
        }
        if ((lane & 3) == 0) {
#pragma unroll
            for (int q = 0; q < 4; q++) {
                int r = rbase + (q >> 1) * 16 + (q & 1) * 8;
                if (r < NN) {
                    if (fuse == 1) {
                        g_als[r * 8 + hd] = sPs[q];
                        g_ald[r * 8 + hd] = sPd[q];
                    } else {
                        int h2 = wcol >> 7, q2 = (wcol >> 5) & 3;
                        size_t pi = ((size_t)q2 * NN + r) * 8 + h2;
                        g_alsP[pi] = sPs[q];
                        g_aldP[pi] = sPd[q];
                    }
                }
            }
        }
    }
}

// ---------------- sum the 4 quarter-partials (layer 2 coef) -----------------
__global__ void k_sum4() {
    int i = blockIdx.x * blockDim.x + threadIdx.x;
    if (i >= NN * HEADS) return;
    const size_t S = (size_t)NN * HEADS;
    g_als[i] = g_alsP[i] + g_alsP[S + i] + g_alsP[2 * S + i] + g_alsP[3 * S + i];
    g_ald[i] = g_aldP[i] + g_aldP[S + i] + g_aldP[2 * S + i] + g_aldP[3 * S + i];
}

// ---------------- softmax: warp per node, all 8 heads vectorized ------------
__global__ void k_alpha() {
    int gw = (blockIdx.x * blockDim.x + threadIdx.x) >> 5;
    int lane = threadIdx.x & 31;
    if (gw >= NN) return;
    int b = g_rowptr[gw], e = g_rowptr[gw + 1];
    float ad[8];
#pragma unroll
    for (int h = 0; h < 8; h++) ad[h] = g_ald[gw * 8 + h];
    float mx[8];
#pragma unroll
    for (int h = 0; h < 8; h++) mx[h] = -INFINITY;
    for (int j = b + lane; j < e; j += 32) {
        int col = g_col[j];
        const float* sp = g_als + col * 8;
        float v[8];
#pragma unroll
        for (int h = 0; h < 8; h++) {
            float t = sp[h] + ad[h];
            v[h] = t > 0.f ? t : 0.2f * t;
            mx[h] = fmaxf(mx[h], v[h]);
        }
        float4* op = (float4*)(g_alpha + (size_t)j * 8);
        op[0] = make_float4(v[0], v[1], v[2], v[3]);
        op[1] = make_float4(v[4], v[5], v[6], v[7]);
    }
#pragma unroll
    for (int h = 0; h < 8; h++)
#pragma unroll
        for (int o = 16; o; o >>= 1)
            mx[h] = fmaxf(mx[h], __shfl_xor_sync(0xffffffffu, mx[h], o));
    float den[8] = {};
    for (int j = b + lane; j < e; j += 32) {
        float4* op = (float4*)(g_alpha + (size_t)j * 8);
        float4 v0 = op[0], v1 = op[1];
        float ex[8];
        ex[0] = expf(v0.x - mx[0]); ex[1] = expf(v0.y - mx[1]);
        ex[2] = expf(v0.z - mx[2]); ex[3] = expf(v0.w - mx[3]);
        ex[4] = expf(v1.x - mx[4]); ex[5] = expf(v1.y - mx[5]);
        ex[6] = expf(v1.z - mx[6]); ex[7] = expf(v1.w - mx[7]);
#pragma unroll
        for (int h = 0; h < 8; h++) den[h] += ex[h];
        op[0] = make_float4(ex[0], ex[1], ex[2], ex[3]);
        op[1] = make_float4(ex[4], ex[5], ex[6], ex[7]);
    }
#pragma unroll
    for (int h = 0; h < 8; h++) {
#pragma unroll
        for (int o = 16; o; o >>= 1)
            den[h] += __shfl_xor_sync(0xffffffffu, den[h], o);
        den[h] = 1.f / (den[h] + 1e-16f);
    }
    for (int j = b + lane; j < e; j += 32) {
        float4* op = (float4*)(g_alpha + (size_t)j * 8);
        float4 v0 = op[0], v1 = op[1];
        op[0] = make_float4(v0.x * den[0], v0.y * den[1], v0.z * den[2], v0.w * den[3]);
        op[1] = make_float4(v1.x * den[4], v1.y * den[5], v1.z * den[6], v1.w * den[7]);
    }
}

// ---------------- aggregate + LN + residual + ELU (layers 0/1) --------------
__global__ void k_agg01(const float* __restrict__ bias,
                        const float* __restrict__ lng, const float* __restrict__ lnb,
                        int resmode, const float* __restrict__ rw) {
    __shared__ float red[17];
    int n = blockIdx.x;
    int t = threadIdx.x;
    int b = g_rowptr[n], e = g_rowptr[n + 1];
    int hd = t >> 5;
    float acc = 0.f;
    for (int j = b; j < e; j++) {
        float a = g_alpha[(size_t)j * HEADS + hd];
        acc += a * g_h[(size_t)g_col[j] * D0 + t];
    }
    float v = acc + bias[t];
    float s = v, q = v * v;
#pragma unroll
    for (int o = 16; o; o >>= 1) {
        s += __shfl_down_sync(0xffffffffu, s, o);
        q += __shfl_down_sync(0xffffffffu, q, o);
    }
    int w = t >> 5, lane = t & 31;
    if (lane == 0) { red[w] = s; red[8 + w] = q; }
    __syncthreads();
    if (t == 0) {
        float S = 0.f, Q = 0.f;
        for (int i = 0; i < 8; i++) { S += red[i]; Q += red[8 + i]; }
        red[0] = S; red[8] = Q;
    }
    __syncthreads();
    float mu = red[0] * (1.f / 256.f);
    float var = red[8] * (1.f / 256.f) - mu * mu;
    float ln = (v - mu) * rsqrtf(var + 1e-5f) * lng[t] + lnb[t];
    float sg = 1.f / (1.f + expf(-rw[0]));
    float rv = resmode ? g_feat[(size_t)n * D0 + t] : g_res[(size_t)n * D0 + t];
    float o = ln + sg * rv;
    float ov = o > 0.f ? o : expm1f(o);
    size_t idx = (size_t)n * D0 + t;
    g_feat[idx] = ov;
    __nv_bfloat16 hi = __float2bfloat16(ov);
    g_ahi[idx] = hi;
    g_alo[idx] = __float2bfloat16(ov - __bfloat162float(hi));
}

// ---------------- layer 2 aggregation ---------------------------------------
__global__ void k_agg2(const float* __restrict__ b2,
                       const float* __restrict__ lng, const float* __restrict__ lnb,
                       const float* __restrict__ rw, float* __restrict__ out) {
    __shared__ float red[9];
    int n = blockIdx.x;
    int c = threadIdx.x;
    int b = g_rowptr[n], e = g_rowptr[n + 1];
    float acc[8] = {0.f, 0.f, 0.f, 0.f, 0.f, 0.f, 0.f, 0.f};
    for (int j = b; j < e; j++) {
        const float* hp = g_h + (size_t)g_col[j] * D2 + c;
        const float* ap = g_alpha + (size_t)j * HEADS;
#pragma unroll
        for (int h = 0; h < 8; h++) acc[h] += ap[h] * hp[h * OUTC];
    }
    float v = (acc[0] + acc[1] + acc[2] + acc[3] + acc[4] + acc[5] + acc[6] + acc[7]) * 0.125f
              + b2[c];
    float s = v, q = v * v;
#pragma unroll
    for (int o = 16; o; o >>= 1) {
        s += __shfl_down_sync(0xffffffffu, s, o);
        q += __shfl_down_sync(0xffffffffu, q, o);
    }
    int w = c >> 5, lane = c & 31;
    if (lane == 0) { red[w] = s; red[4 + w] = q; }
    __syncthreads();
    if (c == 0) {
        float S = 0.f, Q = 0.f;
        for (int i = 0; i < 4; i++) { S += red[i]; Q += red[4 + i]; }
        red[0] = S; red[4] = Q;
    }
    __syncthreads();
    float mu = red[0] * (1.f / 128.f);
    float var = red[4] * (1.f / 128.f) - mu * mu;
    float ln = (v - mu) * rsqrtf(var + 1e-5f) * lng[c] + lnb[c];
    float sg = 1.f / (1.f + expf(-rw[0]));
    out[(size_t)n * OUTC + c] = ln + sg * g_res[(size_t)n * OUTC + c];
}

// ---------------------------------------------------------------------------
extern "C" void kernel_launch(void* const* d_in, const int* in_sizes, int n_in,
                              void* d_out, int out_size) {
    const float* x    = (const float*)d_in[0];
    const void*  ei   = d_in[1];
    const float* W0  = (const float*)d_in[2];
    const float* b0  = (const float*)d_in[3];
    const float* as0 = (const float*)d_in[4];
    const float* ad0 = (const float*)d_in[5];
    const float* lng0 = (const float*)d_in[6];
    const float* lnb0 = (const float*)d_in[7];
    const float* rW0 = (const float*)d_in[8];
    const float* rb0 = (const float*)d_in[9];
    const float* rw0 = (const float*)d_in[10];
    const float* W1  = (const float*)d_in[11];
    const float* b1  = (const float*)d_in[12];
    const float* as1 = (const float*)d_in[13];
    const float* ad1 = (const float*)d_in[14];
    const float* lng1 = (const float*)d_in[15];
    const float* lnb1 = (const float*)d_in[16];
    const float* rw1 = (const float*)d_in[17];
    const float* W2  = (const float*)d_in[18];
    const float* b2  = (const float*)d_in[19];
    const float* as2 = (const float*)d_in[20];
    const float* ad2 = (const float*)d_in[21];
    const float* lng2 = (const float*)d_in[22];
    const float* lnb2 = (const float*)d_in[23];
    const float* rW2 = (const float*)d_in[24];
    const float* rb2 = (const float*)d_in[25];
    const float* rw2 = (const float*)d_in[26];
    float* out = (float*)d_out;

    // one-time side stream + fork/join events (created pre-capture on the
    // correctness call; identical captured work every call)
    static cudaStream_t s1 = nullptr;
    static cudaEvent_t evF = nullptr, evJ = nullptr;
    if (!s1) {
        cudaStreamCreateWithFlags(&s1, cudaStreamNonBlocking);
        cudaEventCreateWithFlags(&evF, cudaEventDisableTiming);
        cudaEventCreateWithFlags(&evJ, cudaEventDisableTiming);
    }

    const int GY = (NN + 127) / 128;   // 157

    // ---- fork: weight prep + layer-0 GEMM on s1, CSR build on main ----
    cudaEventRecord(evF, 0);
    cudaStreamWaitEvent(s1, evF, 0);

    k_cvtW<<<(64 * 256 + 255) / 256, 256, 0, s1>>>(W0,  OFF_W0,  64, 256);
    k_cvtW<<<(64 * 256 + 255) / 256, 256, 0, s1>>>(rW0, OFF_RW0, 64, 256);
    k_cvtA<<<(NN * 64 + 255) / 256, 256, 0, s1>>>(x, 64);
    k_mma<<<dim3(8, GY), 256, 0, s1>>>(64, OFF_W0, rb0, 256, 256, 256, 1, as0, ad0);
    k_cvtW<<<(256 * 256 + 255) / 256, 256, 0, s1>>>(W1, OFF_W1, 256, 256);
    k_cvtW<<<(256 * 1024 + 255) / 256, 256, 0, s1>>>(W2, OFF_W2, 256, 1024);
    k_cvtW<<<(256 * 128 + 255) / 256, 256, 0, s1>>>(rW2, OFF_RW2, 256, 128);
    cudaEventRecord(evJ, s1);

    k_deg_init<<<(NN + 255) / 256, 256>>>();
    k_detect<<<256, 256>>>((const unsigned long long*)ei);
    k_count<<<(EE + 255) / 256, 256>>>(ei);
    k_scanA<<<NPART, 256>>>();
    k_scanB<<<1, 128>>>();
    k_scanC<<<NPART, 256>>>();
    k_fill<<<(TOTE + 255) / 256, 256>>>(ei);

    cudaStreamWaitEvent(0, evJ, 0);   // join

    const int ABLK = (NN * 32 + 255) / 256;

    // ---- layer 0 ----
    k_alpha<<<ABLK, 256>>>();
    k_agg01<<<NN, 256>>>(b0, lng0, lnb0, 0, rw0);

    // ---- layer 1 ----
    k_mma<<<dim3(4, GY), 256>>>(256, OFF_W1, nullptr, 256, 256, 256, 1, as1, ad1);
    k_alpha<<<ABLK, 256>>>();
    k_agg01<<<NN, 256>>>(b1, lng1, lnb1, 1, rw1);

    // ---- layer 2 ----
    k_mma<<<dim3(18, GY), 256>>>(256, OFF_W2, rb2, 1024, 1024, 128, 2, as2, ad2);
    k_sum4<<<(NN * HEADS + 255) / 256, 256>>>();
    k_alpha<<<ABLK, 256>>>();
    k_agg2<<<NN, 128>>>(b2, lng2, lnb2, rw2, out);
}

// round 17
// speedup vs baseline: 1.0139x; 1.0139x over previous
#include <cuda_runtime.h>
#include <cuda_bf16.h>
#include <math.h>
#include <stdint.h>

#define NN 20000
#define EE 320000
#define TOTE (EE + NN)
#define HEADS 8
#define HID 32
#define OUTC 128
#define D0 256
#define D2 1024
#define NPART 79                 // ceil(NN/256)

// ---------------- scratch ---------------------------------------------------
__device__ float g_h[(size_t)NN * D2];
__device__ float g_feat[(size_t)NN * D0];
__device__ float g_res[(size_t)NN * D0];
__device__ float g_als[NN * HEADS];
__device__ float g_ald[NN * HEADS];
__device__ float g_alsP[(size_t)4 * NN * HEADS];
__device__ float g_aldP[(size_t)4 * NN * HEADS];
__device__ float g_alpha[(size_t)TOTE * HEADS];
__device__ int   g_deg[NN];
__device__ int   g_rowptr[NN + 1];
__device__ int   g_cursor[NN];
__device__ int   g_col[TOTE];
__device__ int   g_is32;
__device__ int   g_part[NPART];

// bf16 split operands
__device__ __nv_bfloat16 g_ahi[(size_t)NN * D0];
__device__ __nv_bfloat16 g_alo[(size_t)NN * D0];
#define WSZ 393216
#define OFF_W0  0u            // 512 rows x 64  (W0 cols 0-255, rW0 cols 256-511)
#define OFF_RW0 16384u
#define OFF_W1  32768u        // 256 rows x 256
#define OFF_W2  98304u        // 1152 rows x 256 (W2 cols 0-1023, rW2 cols 1024-1151)
#define OFF_RW2 360448u
__device__ __nv_bfloat16 g_whi[WSZ];
__device__ __nv_bfloat16 g_wlo[WSZ];

// ---------------- helpers ----------------------------------------------------
__device__ __forceinline__ uint32_t smem_u32(const void* p) {
    uint32_t r;
    asm("{ .reg .u64 t; cvta.to.shared.u64 t, %1; cvt.u32.u64 %0, t; }" : "=r"(r) : "l"(p));
    return r;
}

__device__ __forceinline__ void ldsm4(uint32_t* r, uint32_t addr) {
    asm volatile("ldmatrix.sync.aligned.m8n8.x4.shared.b16 {%0,%1,%2,%3}, [%4];"
                 : "=r"(r[0]), "=r"(r[1]), "=r"(r[2]), "=r"(r[3]) : "r"(addr));
}
__device__ __forceinline__ void mma16816(float* c, const uint32_t* a, const uint32_t* b) {
    asm volatile("mma.sync.aligned.m16n8k16.row.col.f32.bf16.bf16.f32 "
                 "{%0,%1,%2,%3}, {%4,%5,%6,%7}, {%8,%9}, {%0,%1,%2,%3};"
                 : "+f"(c[0]), "+f"(c[1]), "+f"(c[2]), "+f"(c[3])
                 : "r"(a[0]), "r"(a[1]), "r"(a[2]), "r"(a[3]), "r"(b[0]), "r"(b[1]));
}

// ---------------- edge dtype detection -------------------------------------
__global__ void k_detect(const unsigned long long* __restrict__ p) {
    int i = blockIdx.x * blockDim.x + threadIdx.x;
    bool big = false;
    for (int j = i; j < EE; j += gridDim.x * blockDim.x)
        if (p[j] >= (unsigned long long)NN) big = true;
    if (__syncthreads_or(big) && threadIdx.x == 0) atomicOr(&g_is32, 1);
}

__device__ __forceinline__ int edge_at(const void* ei, int idx) {
    if (g_is32) return ((const int*)ei)[idx];
    return (int)((const long long*)ei)[idx];
}

// ---------------- CSR build -------------------------------------------------
__global__ void k_deg_init() {
    int i = blockIdx.x * blockDim.x + threadIdx.x;
    if (i < NN) g_deg[i] = 1;
    if (i == 0) g_is32 = 0;
}

__global__ void k_count(const void* __restrict__ ei) {
    int e = blockIdx.x * blockDim.x + threadIdx.x;
    if (e < EE) atomicAdd(&g_deg[edge_at(ei, EE + e)], 1);
}

__global__ void k_scanA() {
    __shared__ int sh[256];
    int i = blockIdx.x * 256 + threadIdx.x;
    sh[threadIdx.x] = (i < NN) ? g_deg[i] : 0;
    __syncthreads();
    for (int o = 128; o; o >>= 1) {
        if (threadIdx.x < o) sh[threadIdx.x] += sh[threadIdx.x + o];
        __syncthreads();
    }
    if (threadIdx.x == 0) g_part[blockIdx.x] = sh[0];
}

__global__ void k_scanB() {
    __shared__ int s[NPART];
    int t = threadIdx.x;
    if (t < NPART) s[t] = g_part[t];
    __syncthreads();
    if (t == 0) {
        int run = 0;
        for (int i = 0; i < NPART; i++) { int v = s[i]; s[i] = run; run += v; }
        g_rowptr[NN] = run;
    }
    __syncthreads();
    if (t < NPART) g_part[t] = s[t];
}

__global__ void k_scanC() {
    __shared__ int sh[256];
    int i = blockIdx.x * 256 + threadIdx.x;
    int v = (i < NN) ? g_deg[i] : 0;
    sh[threadIdx.x] = v;
    __syncthreads();
    for (int o = 1; o < 256; o <<= 1) {
        int a = (threadIdx.x >= o) ? sh[threadIdx.x - o] : 0;
        __syncthreads();
        sh[threadIdx.x] += a;
        __syncthreads();
    }
    if (i < NN) {
        int ex = sh[threadIdx.x] - v + g_part[blockIdx.x];
        g_rowptr[i] = ex;
        g_cursor[i] = ex;
    }
}

__global__ void k_fill(const void* __restrict__ ei) {
    int idx = blockIdx.x * blockDim.x + threadIdx.x;
    if (idx >= TOTE) return;
    int s, d;
    if (idx < EE) { s = edge_at(ei, idx); d = edge_at(ei, EE + idx); }
    else          { s = d = idx - EE; }
    int pos = atomicAdd(&g_cursor[d], 1);
    g_col[pos] = s;
}

// ---------------- bf16 split conversions ------------------------------------
__global__ void k_cvtA(const float* __restrict__ src, int Kt) {
    size_t idx = (size_t)blockIdx.x * blockDim.x + threadIdx.x;
    size_t tot = (size_t)NN * Kt;
    if (idx >= tot) return;
    float v = src[idx];
    __nv_bfloat16 hi = __float2bfloat16(v);
    g_ahi[idx] = hi;
    g_alo[idx] = __float2bfloat16(v - __bfloat162float(hi));
}

__global__ void k_cvtW(const float* __restrict__ W, unsigned woff, int K, int N) {
    int idx = blockIdx.x * blockDim.x + threadIdx.x;
    if (idx >= K * N) return;
    int k = idx / N, n = idx % N;
    float v = W[idx];
    __nv_bfloat16 hi = __float2bfloat16(v);
    g_whi[woff + (size_t)n * K + k] = hi;
    g_wlo[woff + (size_t)n * K + k] = __float2bfloat16(v - __bfloat162float(hi));
}

// ---------------- tensor-core GEMM via mma.sync (bf16 3-term split) ---------
// Double-buffered dynamic smem (one __syncthreads per K-chunk).
// C cols [0,split) -> g_h (stride strideH); cols [split,..) -> g_res + bias.
// fuse=1: 32-wide heads -> g_als/g_ald. fuse=2: 128-wide heads -> quarter partials.
#define RP 40
// per-buffer byte offsets within one stage buffer (total 30720 B):
#define SB_AH 0u
#define SB_AL 10240u
#define SB_BH 20480u
#define SB_BL 25600u
#define SB_SZ 30720u
#define SMEM_DYN (2 * SB_SZ)     // 61440

__global__ __launch_bounds__(256) void k_mma(int Kt, unsigned woff,
                                             const float* __restrict__ bias,
                                             int split, int strideH, int strideR,
                                             int fuse,
                                             const float* __restrict__ a_s,
                                             const float* __restrict__ a_d) {
    extern __shared__ __nv_bfloat16 dyn[];
    __shared__ float sAS[256], sAD[256];

    const int tid = threadIdx.x, lane = tid & 31, wid = tid >> 5;
    const int m0 = (wid & 3) << 5;
    const int n0 = (wid >> 2) << 5;
    const int bm = blockIdx.y * 128, bn = blockIdx.x * 64;

    const uint32_t aDyn = smem_u32(dyn);
    char* cdyn = (char*)dyn;

    if (fuse == 1) { sAS[tid] = a_s[tid]; sAD[tid] = a_d[tid]; }
    else if (fuse == 2 && bn < split && tid < 64) {
        sAS[tid] = a_s[bn + tid];
        sAD[tid] = a_d[bn + tid];
    }

    const int ar0 = tid >> 2, ac = (tid & 3) * 8;
    const int ar1 = (tid + 256) >> 2;
    const int br = tid >> 2;
    const int am0 = bm + ar0, am1 = bm + ar1;
    const size_t bb = (size_t)(bn + br) * Kt + ac;
    const uint32_t stA = (uint32_t)(ar0 * RP + ac) * 2;
    const uint32_t stA1 = (uint32_t)(ar1 * RP + ac) * 2;
    const uint32_t stB = (uint32_t)(br * RP + ac) * 2;

    float acc[2][4][4] = {};
    uint4 pAh0, pAl0, pAh1, pAl1, pBh, pBl;
    const uint4 z4 = make_uint4(0, 0, 0, 0);

    // prefetch + stage chunk 0 into buffer 0
    pAh0 = (am0 < NN) ? *(const uint4*)(g_ahi + (size_t)am0 * Kt + ac) : z4;
    pAl0 = (am0 < NN) ? *(const uint4*)(g_alo + (size_t)am0 * Kt + ac) : z4;
    pAh1 = (am1 < NN) ? *(const uint4*)(g_ahi + (size_t)am1 * Kt + ac) : z4;
    pAl1 = (am1 < NN) ? *(const uint4*)(g_alo + (size_t)am1 * Kt + ac) : z4;
    pBh = *(const uint4*)(g_whi + woff + bb);
    pBl = *(const uint4*)(g_wlo + woff + bb);
    *(uint4*)(cdyn + SB_AH + stA)  = pAh0;
    *(uint4*)(cdyn + SB_AL + stA)  = pAl0;
    *(uint4*)(cdyn + SB_AH + stA1) = pAh1;
    *(uint4*)(cdyn + SB_AL + stA1) = pAl1;
    *(uint4*)(cdyn + SB_BH + stB)  = pBh;
    *(uint4*)(cdyn + SB_BL + stB)  = pBl;

    // precomputed ldmatrix lane offsets
    const uint32_t offA0 = (uint32_t)((m0 + (lane & 15)) * RP + ((lane >> 4) << 3)) * 2;
    const uint32_t offA1 = (uint32_t)((m0 + 16 + (lane & 15)) * RP + ((lane >> 4) << 3)) * 2;
    const uint32_t offB  = (uint32_t)((n0 + (lane & 7)) * RP + (((lane >> 3) & 1) << 3)) * 2;
    const uint32_t selB  = (lane < 16) ? SB_BH : SB_BL;

    const int nch = Kt >> 5;
    for (int ch = 0; ch < nch; ch++) {
        __syncthreads();
        const uint32_t base = aDyn + (ch & 1) * SB_SZ;
        char* nbuf = cdyn + ((ch + 1) & 1) * SB_SZ;

        if (ch + 1 < nch) {
            const int k1 = (ch + 1) << 5;
            pAh0 = (am0 < NN) ? *(const uint4*)(g_ahi + (size_t)am0 * Kt + k1 + ac) : z4;
            pAl0 = (am0 < NN) ? *(const uint4*)(g_alo + (size_t)am0 * Kt + k1 + ac) : z4;
            pAh1 = (am1 < NN) ? *(const uint4*)(g_ahi + (size_t)am1 * Kt + k1 + ac) : z4;
            pAl1 = (am1 < NN) ? *(const uint4*)(g_alo + (size_t)am1 * Kt + k1 + ac) : z4;
            pBh = *(const uint4*)(g_whi + woff + bb + k1);
            pBl = *(const uint4*)(g_wlo + woff + bb + k1);
        }

#pragma unroll
        for (int ks = 0; ks < 32; ks += 16) {
            uint32_t ah[2][4], al[2][4], bm4[4][4];
            const uint32_t kso = (uint32_t)ks * 2;
#pragma unroll
            for (int mi = 0; mi < 2; mi++) {
                uint32_t off = (mi ? offA1 : offA0) + kso;
                ldsm4(ah[mi], base + SB_AH + off);
                ldsm4(al[mi], base + SB_AL + off);
            }
#pragma unroll
            for (int nj = 0; nj < 4; nj++) {
                // merged hi+lo B load: lanes 0-15 -> sBh tiles, 16-31 -> sBl tiles
                uint32_t addr = base + selB + offB + (uint32_t)(nj * 8 * RP) * 2 + kso;
                ldsm4(bm4[nj], addr);
            }
#pragma unroll
            for (int mi = 0; mi < 2; mi++)
#pragma unroll
                for (int nj = 0; nj < 4; nj++) {
                    mma16816(acc[mi][nj], ah[mi], &bm4[nj][0]);      // Ahi*Bhi
                    mma16816(acc[mi][nj], ah[mi], &bm4[nj][2]);      // Ahi*Blo
                    mma16816(acc[mi][nj], al[mi], &bm4[nj][0]);      // Alo*Bhi
                }
        }

        if (ch + 1 < nch) {
            *(uint4*)(nbuf + SB_AH + stA)  = pAh0;
            *(uint4*)(nbuf + SB_AL + stA)  = pAl0;
            *(uint4*)(nbuf + SB_AH + stA1) = pAh1;
            *(uint4*)(nbuf + SB_AL + stA1) = pAl1;
            *(uint4*)(nbuf + SB_BH + stB)  = pBh;
            *(uint4*)(nbuf + SB_BL + stB)  = pBl;
        }
    }

    // ---- epilogue ----
    const int wcol = bn + n0;
    const int side = wcol < split;
    const int hd = wcol >> 5;
    const int rbase = bm + m0 + (lane >> 2);
    float sPs[4] = {}, sPd[4] = {};

#pragma unroll
    for (int mi = 0; mi < 2; mi++) {
#pragma unroll
        for (int nj = 0; nj < 4; nj++) {
            int cg = wcol + nj * 8 + (lane & 3) * 2;
            int r0 = rbase + mi * 16, r1 = r0 + 8;
            float v0 = acc[mi][nj][0], v1 = acc[mi][nj][1];
            float v2 = acc[mi][nj][2], v3 = acc[mi][nj][3];
            if (side) {
                if (r0 < NN) *(float2*)(g_h + (size_t)r0 * strideH + cg) = make_float2(v0, v1);
                if (r1 < NN) *(float2*)(g_h + (size_t)r1 * strideH + cg) = make_float2(v2, v3);
                if (fuse) {
                    int cc = (fuse == 1) ? ((hd << 5) | (cg & 31)) : (cg - bn);
                    float as0 = sAS[cc], as1 = sAS[cc + 1];
                    float ad0 = sAD[cc], ad1 = sAD[cc + 1];
                    sPs[mi * 2 + 0] += v0 * as0 + v1 * as1;
                    sPs[mi * 2 + 1] += v2 * as0 + v3 * as1;
                    sPd[mi * 2 + 0] += v0 * ad0 + v1 * ad1;
                    sPd[mi * 2 + 1] += v2 * ad0 + v3 * ad1;
                }
            } else {
                int cr = cg - split;
                float bx = bias ? bias[cr] : 0.f;
                float by = bias ? bias[cr + 1] : 0.f;
                if (r0 < NN) *(float2*)(g_res + (size_t)r0 * strideR + cr) = make_float2(v0 + bx, v1 + by);
                if (r1 < NN) *(float2*)(g_res + (size_t)r1 * strideR + cr) = make_float2(v2 + bx, v3 + by);
            }
        }
    }

    if (side && fuse) {
#pragma unroll
        for (int q = 0; q < 4; q++) {
            sPs[q] += __shfl_xor_sync(0xffffffffu, sPs[q], 1);
            sPs[q] += __shfl_xor_sync(0xffffffffu, sPs[q], 2);
            sPd[q] += __shfl_xor_sync(0xffffffffu, sPd[q], 1);
            sPd[q] += __shfl_xor_sync(0xffffffffu, sPd[q], 2);
        }
        if ((lane & 3) == 0) {
#pragma unroll
            for (int q = 0; q < 4; q++) {
                int r = rbase + (q >> 1) * 16 + (q & 1) * 8;
                if (r < NN) {
                    if (fuse == 1) {
                        g_als[r * 8 + hd] = sPs[q];
                        g_ald[r * 8 + hd] = sPd[q];
                    } else {
                        int h2 = wcol >> 7, q2 = (wcol >> 5) & 3;
                        size_t pi = ((size_t)q2 * NN + r) * 8 + h2;
                        g_alsP[pi] = sPs[q];
                        g_aldP[pi] = sPd[q];
                    }
                }
            }
        }
    }
}

// ---------------- sum the 4 quarter-partials (layer 2 coef) -----------------
__global__ void k_sum4() {
    int i = blockIdx.x * blockDim.x + threadIdx.x;
    if (i >= NN * HEADS) return;
    const size_t S = (size_t)NN * HEADS;
    g_als[i] = g_alsP[i] + g_alsP[S + i] + g_alsP[2 * S + i] + g_alsP[3 * S + i];
    g_ald[i] = g_aldP[i] + g_aldP[S + i] + g_aldP[2 * S + i] + g_aldP[3 * S + i];
}

// ---------------- softmax: warp per node, all 8 heads vectorized ------------
__global__ void k_alpha() {
    int gw = (blockIdx.x * blockDim.x + threadIdx.x) >> 5;
    int lane = threadIdx.x & 31;
    if (gw >= NN) return;
    int b = g_rowptr[gw], e = g_rowptr[gw + 1];
    float ad[8];
#pragma unroll
    for (int h = 0; h < 8; h++) ad[h] = g_ald[gw * 8 + h];
    float mx[8];
#pragma unroll
    for (int h = 0; h < 8; h++) mx[h] = -INFINITY;
    for (int j = b + lane; j < e; j += 32) {
        int col = g_col[j];
        const float* sp = g_als + col * 8;
        float v[8];
#pragma unroll
        for (int h = 0; h < 8; h++) {
            float t = sp[h] + ad[h];
            v[h] = t > 0.f ? t : 0.2f * t;
            mx[h] = fmaxf(mx[h], v[h]);
        }
        float4* op = (float4*)(g_alpha + (size_t)j * 8);
        op[0] = make_float4(v[0], v[1], v[2], v[3]);
        op[1] = make_float4(v[4], v[5], v[6], v[7]);
    }
#pragma unroll
    for (int h = 0; h < 8; h++)
#pragma unroll
        for (int o = 16; o; o >>= 1)
            mx[h] = fmaxf(mx[h], __shfl_xor_sync(0xffffffffu, mx[h], o));
    float den[8] = {};
    for (int j = b + lane; j < e; j += 32) {
        float4* op = (float4*)(g_alpha + (size_t)j * 8);
        float4 v0 = op[0], v1 = op[1];
        float ex[8];
        ex[0] = expf(v0.x - mx[0]); ex[1] = expf(v0.y - mx[1]);
        ex[2] = expf(v0.z - mx[2]); ex[3] = expf(v0.w - mx[3]);
        ex[4] = expf(v1.x - mx[4]); ex[5] = expf(v1.y - mx[5]);
        ex[6] = expf(v1.z - mx[6]); ex[7] = expf(v1.w - mx[7]);
#pragma unroll
        for (int h = 0; h < 8; h++) den[h] += ex[h];
        op[0] = make_float4(ex[0], ex[1], ex[2], ex[3]);
        op[1] = make_float4(ex[4], ex[5], ex[6], ex[7]);
    }
#pragma unroll
    for (int h = 0; h < 8; h++) {
#pragma unroll
        for (int o = 16; o; o >>= 1)
            den[h] += __shfl_xor_sync(0xffffffffu, den[h], o);
        den[h] = 1.f / (den[h] + 1e-16f);
    }
    for (int j = b + lane; j < e; j += 32) {
        float4* op = (float4*)(g_alpha + (size_t)j * 8);
        float4 v0 = op[0], v1 = op[1];
        op[0] = make_float4(v0.x * den[0], v0.y * den[1], v0.z * den[2], v0.w * den[3]);
        op[1] = make_float4(v1.x * den[4], v1.y * den[5], v1.z * den[6], v1.w * den[7]);
    }
}

// ---------------- aggregate + LN + residual + ELU (layers 0/1) --------------
__global__ void k_agg01(const float* __restrict__ bias,
                        const float* __restrict__ lng, const float* __restrict__ lnb,
                        int resmode, const float* __restrict__ rw) {
    __shared__ float red[17];
    int n = blockIdx.x;
    int t = threadIdx.x;
    int b = g_rowptr[n], e = g_rowptr[n + 1];
    int hd = t >> 5;
    float acc = 0.f;
    for (int j = b; j < e; j++) {
        float a = g_alpha[(size_t)j * HEADS + hd];
        acc += a * g_h[(size_t)g_col[j] * D0 + t];
    }
    float v = acc + bias[t];
    float s = v, q = v * v;
#pragma unroll
    for (int o = 16; o; o >>= 1) {
        s += __shfl_down_sync(0xffffffffu, s, o);
        q += __shfl_down_sync(0xffffffffu, q, o);
    }
    int w = t >> 5, lane = t & 31;
    if (lane == 0) { red[w] = s; red[8 + w] = q; }
    __syncthreads();
    if (t == 0) {
        float S = 0.f, Q = 0.f;
        for (int i = 0; i < 8; i++) { S += red[i]; Q += red[8 + i]; }
        red[0] = S; red[8] = Q;
    }
    __syncthreads();
    float mu = red[0] * (1.f / 256.f);
    float var = red[8] * (1.f / 256.f) - mu * mu;
    float ln = (v - mu) * rsqrtf(var + 1e-5f) * lng[t] + lnb[t];
    float sg = 1.f / (1.f + expf(-rw[0]));
    float rv = resmode ? g_feat[(size_t)n * D0 + t] : g_res[(size_t)n * D0 + t];
    float o = ln + sg * rv;
    float ov = o > 0.f ? o : expm1f(o);
    size_t idx = (size_t)n * D0 + t;
    g_feat[idx] = ov;
    __nv_bfloat16 hi = __float2bfloat16(ov);
    g_ahi[idx] = hi;
    g_alo[idx] = __float2bfloat16(ov - __bfloat162float(hi));
}

// ---------------- layer 2 aggregation ---------------------------------------
__global__ void k_agg2(const float* __restrict__ b2,
                       const float* __restrict__ lng, const float* __restrict__ lnb,
                       const float* __restrict__ rw, float* __restrict__ out) {
    __shared__ float red[9];
    int n = blockIdx.x;
    int c = threadIdx.x;
    int b = g_rowptr[n], e = g_rowptr[n + 1];
    float acc[8] = {0.f, 0.f, 0.f, 0.f, 0.f, 0.f, 0.f, 0.f};
    for (int j = b; j < e; j++) {
        const float* hp = g_h + (size_t)g_col[j] * D2 + c;
        const float* ap = g_alpha + (size_t)j * HEADS;
#pragma unroll
        for (int h = 0; h < 8; h++) acc[h] += ap[h] * hp[h * OUTC];
    }
    float v = (acc[0] + acc[1] + acc[2] + acc[3] + acc[4] + acc[5] + acc[6] + acc[7]) * 0.125f
              + b2[c];
    float s = v, q = v * v;
#pragma unroll
    for (int o = 16; o; o >>= 1) {
        s += __shfl_down_sync(0xffffffffu, s, o);
        q += __shfl_down_sync(0xffffffffu, q, o);
    }
    int w = c >> 5, lane = c & 31;
    if (lane == 0) { red[w] = s; red[4 + w] = q; }
    __syncthreads();
    if (c == 0) {
        float S = 0.f, Q = 0.f;
        for (int i = 0; i < 4; i++) { S += red[i]; Q += red[4 + i]; }
        red[0] = S; red[4] = Q;
    }
    __syncthreads();
    float mu = red[0] * (1.f / 128.f);
    float var = red[4] * (1.f / 128.f) - mu * mu;
    float ln = (v - mu) * rsqrtf(var + 1e-5f) * lng[c] + lnb[c];
    float sg = 1.f / (1.f + expf(-rw[0]));
    out[(size_t)n * OUTC + c] = ln + sg * g_res[(size_t)n * OUTC + c];
}

// ---------------------------------------------------------------------------
extern "C" void kernel_launch(void* const* d_in, const int* in_sizes, int n_in,
                              void* d_out, int out_size) {
    const float* x    = (const float*)d_in[0];
    const void*  ei   = d_in[1];
    const float* W0  = (const float*)d_in[2];
    const float* b0  = (const float*)d_in[3];
    const float* as0 = (const float*)d_in[4];
    const float* ad0 = (const float*)d_in[5];
    const float* lng0 = (const float*)d_in[6];
    const float* lnb0 = (const float*)d_in[7];
    const float* rW0 = (const float*)d_in[8];
    const float* rb0 = (const float*)d_in[9];
    const float* rw0 = (const float*)d_in[10];
    const float* W1  = (const float*)d_in[11];
    const float* b1  = (const float*)d_in[12];
    const float* as1 = (const float*)d_in[13];
    const float* ad1 = (const float*)d_in[14];
    const float* lng1 = (const float*)d_in[15];
    const float* lnb1 = (const float*)d_in[16];
    const float* rw1 = (const float*)d_in[17];
    const float* W2  = (const float*)d_in[18];
    const float* b2  = (const float*)d_in[19];
    const float* as2 = (const float*)d_in[20];
    const float* ad2 = (const float*)d_in[21];
    const float* lng2 = (const float*)d_in[22];
    const float* lnb2 = (const float*)d_in[23];
    const float* rW2 = (const float*)d_in[24];
    const float* rb2 = (const float*)d_in[25];
    const float* rw2 = (const float*)d_in[26];
    float* out = (float*)d_out;

    static int attrDone = 0;
    if (!attrDone) {
        cudaFuncSetAttribute(k_mma, cudaFuncAttributeMaxDynamicSharedMemorySize, SMEM_DYN);
        attrDone = 1;
    }

    // ---- CSR build ----
    k_deg_init<<<(NN + 255) / 256, 256>>>();
    k_detect<<<256, 256>>>((const unsigned long long*)ei);
    k_count<<<(EE + 255) / 256, 256>>>(ei);
    k_scanA<<<NPART, 256>>>();
    k_scanB<<<1, 128>>>();
    k_scanC<<<NPART, 256>>>();
    k_fill<<<(TOTE + 255) / 256, 256>>>(ei);

    // ---- weight prep ----
    k_cvtW<<<(64 * 256 + 255) / 256, 256>>>(W0,  OFF_W0,  64, 256);
    k_cvtW<<<(64 * 256 + 255) / 256, 256>>>(rW0, OFF_RW0, 64, 256);
    k_cvtW<<<(256 * 256 + 255) / 256, 256>>>(W1, OFF_W1, 256, 256);
    k_cvtW<<<(256 * 1024 + 255) / 256, 256>>>(W2, OFF_W2, 256, 1024);
    k_cvtW<<<(256 * 128 + 255) / 256, 256>>>(rW2, OFF_RW2, 256, 128);

    const int GY = (NN + 127) / 128;   // 157
    const int ABLK = (NN * 32 + 255) / 256;

    // ---- layer 0: merged [W0 | rW0] GEMM, coef fused ----
    k_cvtA<<<(NN * 64 + 255) / 256, 256>>>(x, 64);
    k_mma<<<dim3(8, GY), 256, SMEM_DYN>>>(64, OFF_W0, rb0, 256, 256, 256, 1, as0, ad0);
    k_alpha<<<ABLK, 256>>>();
    k_agg01<<<NN, 256>>>(b0, lng0, lnb0, 0, rw0);

    // ---- layer 1: coef fused ----
    k_mma<<<dim3(4, GY), 256, SMEM_DYN>>>(256, OFF_W1, nullptr, 256, 256, 256, 1, as1, ad1);
    k_alpha<<<ABLK, 256>>>();
    k_agg01<<<NN, 256>>>(b1, lng1, lnb1, 1, rw1);

    // ---- layer 2: merged [W2 | rW2] GEMM, quarter-partial coef ----
    k_mma<<<dim3(18, GY), 256, SMEM_DYN>>>(256, OFF_W2, rb2, 1024, 1024, 128, 2, as2, ad2);
    k_sum4<<<(NN * HEADS + 255) / 256, 256>>>();
    k_alpha<<<ABLK, 256>>>();
    k_agg2<<<NN, 128>>>(b2, lng2, lnb2, rw2, out);
}